// round 15
// baseline (speedup 1.0000x reference)
#include <cuda_runtime.h>
#include <cuda_fp16.h>
#include <cstdint>

#define EDIM 512
#define SLEN 4096
#define BATCH 2
#define NHEAD 8
#define HDIM 64
#define NROWS (BATCH*SLEN)   // 8192
#define QSCALE 0.1803368801111904f   // log2(e)/8, folded into BtQ

// ===========================================================================
// Device scratch (allocation-free rule). Q/K/V single fp16; x hi/lo.
// ===========================================================================
__device__ __half g_xh[NROWS*EDIM], g_xl[NROWS*EDIM];
__device__ __half g_BtQ[EDIM*EDIM], g_BtK[EDIM*EDIM], g_BtV[EDIM*EDIM];
__device__ __half g_Q[NROWS*EDIM], g_K[NROWS*EDIM], g_V[NROWS*EDIM];

// ===========================================================================
// helpers
// ===========================================================================
__device__ __forceinline__ uint32_t smem_to_u32(const void* p) {
    uint32_t a;
    asm("{ .reg .u64 t; cvta.to.shared.u64 t, %1; cvt.u32.u64 %0, t; }"
        : "=r"(a) : "l"(p));
    return a;
}
__device__ __forceinline__ uint32_t pack2h(float a, float b) {
    __half2 t = __floats2half2_rn(a, b);
    return *reinterpret_cast<uint32_t*>(&t);
}
__device__ __forceinline__ float ex2(float x) {
    float y;
    asm("ex2.approx.f32 %0, %1;" : "=f"(y) : "f"(x));
    return y;
}
__device__ __forceinline__ void split1h(float v, float& h, float& l) {
    __half hh = __float2half_rn(v);
    h = __half2float(hh);
    l = v - h;
}
__device__ __forceinline__ void split_pack2h(float a, float b,
                                             uint32_t& hp, uint32_t& lp) {
    float ah, al, bh, bl;
    split1h(a, ah, al); split1h(b, bh, bl);
    hp = pack2h(ah, bh); lp = pack2h(al, bl);
}
__device__ __forceinline__ void mma_f16(float* c, const uint32_t* a,
                                        uint32_t b0, uint32_t b1) {
    asm volatile(
        "mma.sync.aligned.m16n8k16.row.col.f32.f16.f16.f32 "
        "{%0,%1,%2,%3}, {%4,%5,%6,%7}, {%8,%9}, {%0,%1,%2,%3};"
        : "+f"(c[0]), "+f"(c[1]), "+f"(c[2]), "+f"(c[3])
        : "r"(a[0]), "r"(a[1]), "r"(a[2]), "r"(a[3]), "r"(b0), "r"(b1));
}
__device__ __forceinline__ void ldsm_x4(uint32_t* r, uint32_t addr) {
    asm volatile("ldmatrix.sync.aligned.m8n8.x4.shared.b16 {%0,%1,%2,%3}, [%4];"
        : "=r"(r[0]), "=r"(r[1]), "=r"(r[2]), "=r"(r[3]) : "r"(addr));
}
__device__ __forceinline__ void ldsm_x4_t(uint32_t* r, uint32_t addr) {
    asm volatile("ldmatrix.sync.aligned.m8n8.x4.trans.shared.b16 {%0,%1,%2,%3}, [%4];"
        : "=r"(r[0]), "=r"(r[1]), "=r"(r[2]), "=r"(r[3]) : "r"(addr));
}
__device__ __forceinline__ void cpasync16(uint32_t dst, const void* src) {
    asm volatile("cp.async.cg.shared.global [%0], [%1], 16;"
                 :: "r"(dst), "l"(src) : "memory");
}
__device__ __forceinline__ void cp_commit() {
    asm volatile("cp.async.commit_group;" ::: "memory");
}

// ===========================================================================
// prep: x -> fp16 hi/lo ; wv -> fp16 hi only (BtV[j][i] = wv[j][i])
// ===========================================================================
__global__ void split_f16(const float* __restrict__ src,
                          __half* __restrict__ hi,
                          __half* __restrict__ lo, int n4) {
    int i = blockIdx.x * blockDim.x + threadIdx.x;
    if (i >= n4) return;
    float4 v = reinterpret_cast<const float4*>(src)[i];
    uint32_t h0, l0, h1, l1;
    split_pack2h(v.x, v.y, h0, l0);
    split_pack2h(v.z, v.w, h1, l1);
    reinterpret_cast<uint2*>(hi)[i] = make_uint2(h0, h1);
    reinterpret_cast<uint2*>(lo)[i] = make_uint2(l0, l1);
}
__global__ void conv_f16(const float* __restrict__ src,
                         __half* __restrict__ hi, int n4) {
    int i = blockIdx.x * blockDim.x + threadIdx.x;
    if (i >= n4) return;
    float4 v = reinterpret_cast<const float4*>(src)[i];
    reinterpret_cast<uint2*>(hi)[i] =
        make_uint2(pack2h(v.x, v.y), pack2h(v.z, v.w));
}

// ===========================================================================
// fuse: Bt[j][i] = sum_e W[e][i] * R[e][j]  (fp32 compute, fp16 hi out)
// z=0 output is pre-scaled by QSCALE = log2(e)/8 (softmax fold).
// ===========================================================================
__global__ void fuse_weights2(const float* __restrict__ wq,
                              const float* __restrict__ wk,
                              const float* __restrict__ rot,
                              const float* __restrict__ ent) {
    int z = blockIdx.z;
    const float* W = z ? wk : wq;
    const float* R = z ? ent : rot;
    __half* B = z ? g_BtK : g_BtQ;
    float oscale = z ? 1.0f : QSCALE;
    int i0 = blockIdx.y * 64, j0 = blockIdx.x * 64;
    int tid = threadIdx.x;

    __shared__ float As[16*68], Bs[16*68], T[64*65];
    int tm = (tid >> 4) << 2, tn = (tid & 15) << 2;
    int lr = tid >> 4, lc = (tid & 15) << 2;
    float acc[4][4] = {};

    for (int k0 = 0; k0 < EDIM; k0 += 16) {
        *(float4*)&As[lr*68 + lc] = *(const float4*)&W[(k0+lr)*EDIM + i0 + lc];
        *(float4*)&Bs[lr*68 + lc] = *(const float4*)&R[(k0+lr)*EDIM + j0 + lc];
        __syncthreads();
#pragma unroll
        for (int k = 0; k < 16; k++) {
            float4 a = *(const float4*)&As[k*68 + tm];
            float4 b = *(const float4*)&Bs[k*68 + tn];
            float av[4] = {a.x,a.y,a.z,a.w};
            float bv[4] = {b.x,b.y,b.z,b.w};
#pragma unroll
            for (int i = 0; i < 4; i++)
#pragma unroll
                for (int j = 0; j < 4; j++)
                    acc[i][j] = fmaf(av[i], bv[j], acc[i][j]);
        }
        __syncthreads();
    }
#pragma unroll
    for (int i = 0; i < 4; i++)
#pragma unroll
        for (int j = 0; j < 4; j++)
            T[(tm+i)*65 + tn+j] = acc[i][j];
    __syncthreads();
#pragma unroll
    for (int r = 0; r < 4; r++) {
        int jrow = j0 + tm + r;
#pragma unroll
        for (int c = 0; c < 4; c += 2) {
            float v0 = T[(tn+c)*65 + (tm+r)] * oscale;
            float v1 = T[(tn+c+1)*65 + (tm+r)] * oscale;
            *reinterpret_cast<uint32_t*>(&B[jrow*EDIM + i0 + tn + c]) =
                pack2h(v0, v1);
        }
    }
}

// ===========================================================================
// proj: D = x @ M, 128x128 tile/CTA, 256 threads / 8 warps (R7 layout),
// fp16 2-pass: A = x hi/lo, B = Bt hi only. 2-stage cp.async.
// ===========================================================================
#define PJ_ARR 10240                       // bytes per array [128][40] fp16
#define PJ_STAGE (3*PJ_ARR)                // 30720 (xh, xl, B)
#define PJ_SMEM (2*PJ_STAGE)               // 61440

__global__ void __launch_bounds__(256, 2) proj_mma() {
    extern __shared__ char smraw[];
    uint32_t smb = smem_to_u32(smraw);
    int tid = threadIdx.x, lane = tid & 31, warp = tid >> 5;
    int rw = warp & 3, ch = warp >> 2;
    int m0 = blockIdx.x * 128, n0 = blockIdx.y * 128, z = blockIdx.z;

    const __half* B_g = (z==0) ? g_BtQ : (z==1) ? g_BtK : g_BtV;
    __half* D_g = (z==0) ? g_Q : (z==1) ? g_K : g_V;

    int l8 = lane & 7, g4 = lane >> 3;
    int offA = (l8 + ((g4 & 1) ? 8 : 0)) * 40 + ((g4 & 2) ? 8 : 0);
    int offB = (l8 + ((g4 & 2) ? 8 : 0)) * 40 + ((g4 & 1) ? 8 : 0);

    int sr = tid >> 2, sc = (tid & 3) * 8;   // rows sr, sr+64

    auto issue = [&](int it, int st) {
        int k0 = it * 32;
        uint32_t sb = smb + st * PJ_STAGE;
        const __half* srcs[3] = {
            g_xh + (size_t)(m0)*EDIM + k0, g_xl + (size_t)(m0)*EDIM + k0,
            B_g + (size_t)(n0)*EDIM + k0 };
#pragma unroll
        for (int a = 0; a < 3; a++) {
            cpasync16(sb + a*PJ_ARR + (sr*40 + sc)*2, srcs[a] + (size_t)sr*EDIM + sc);
            cpasync16(sb + a*PJ_ARR + ((sr+64)*40 + sc)*2, srcs[a] + (size_t)(sr+64)*EDIM + sc);
        }
        cp_commit();
    };

    float c[2][8][4] = {};
    issue(0, 0);
    issue(1, 1);

    for (int it = 0; it < 16; it++) {
        if (it + 1 < 16) asm volatile("cp.async.wait_group 1;" ::: "memory");
        else             asm volatile("cp.async.wait_group 0;" ::: "memory");
        __syncthreads();
        uint32_t sb = smb + (it & 1) * PJ_STAGE;
        uint32_t aAh = sb, aAl = sb + PJ_ARR, aB = sb + 2*PJ_ARR;

#pragma unroll
        for (int kc = 0; kc < 2; kc++) {
            uint32_t ahf[2][4], alf[2][4];
#pragma unroll
            for (int rg = 0; rg < 2; rg++) {
                uint32_t abase = 2u * (uint32_t)((rw*32 + rg*16)*40 + kc*16 + offA);
                ldsm_x4(ahf[rg], aAh + abase);
                ldsm_x4(alf[rg], aAl + abase);
            }
#pragma unroll
            for (int pp = 0; pp < 2; pp++) {
                uint32_t bhf[2][4];
#pragma unroll
                for (int q = 0; q < 2; q++) {
                    int pr = pp*2 + q;
                    uint32_t bbase = 2u * (uint32_t)((ch*64 + pr*16)*40 + kc*16 + offB);
                    ldsm_x4(bhf[q], aB + bbase);
                }
#pragma unroll
                for (int rg = 0; rg < 2; rg++)
#pragma unroll
                    for (int q = 0; q < 2; q++) {
                        int j = (pp*2 + q)*2;
                        mma_f16(c[rg][j],   ahf[rg], bhf[q][0], bhf[q][1]);
                        mma_f16(c[rg][j+1], ahf[rg], bhf[q][2], bhf[q][3]);
                    }
#pragma unroll
                for (int rg = 0; rg < 2; rg++)
#pragma unroll
                    for (int q = 0; q < 2; q++) {
                        int j = (pp*2 + q)*2;
                        mma_f16(c[rg][j],   alf[rg], bhf[q][0], bhf[q][1]);
                        mma_f16(c[rg][j+1], alf[rg], bhf[q][2], bhf[q][3]);
                    }
            }
        }
        __syncthreads();
        if (it + 2 < 16) issue(it + 2, it & 1);
    }

    int g = lane >> 2, t = lane & 3;
#pragma unroll
    for (int rg = 0; rg < 2; rg++) {
        int mr = m0 + rw*32 + rg*16 + g;
        int b = mr >> 12, s = mr & (SLEN - 1);
#pragma unroll
        for (int j = 0; j < 8; j++) {
            int n = n0 + ch*64 + j*8 + 2*t;
            int hh = n >> 6, d = n & 63;
            size_t i0 = ((size_t)(b*NHEAD + hh)*SLEN + s)*HDIM + d;
            size_t i1 = i0 + 8*HDIM;
            *reinterpret_cast<uint32_t*>(&D_g[i0]) = pack2h(c[rg][j][0], c[rg][j][1]);
            *reinterpret_cast<uint32_t*>(&D_g[i1]) = pack2h(c[rg][j][2], c[rg][j][3]);
        }
    }
}

// ===========================================================================
// attention: CTA = 256 q-rows, 256 threads / 8 warps, 2 CTAs/SM (one wave).
// warp = 32 q-rows (2 x m16 row-groups) x full 64 S-cols.
// K/V L2 traffic halved vs 128-row CTA. Q pre-scaled by log2(e)/8 =>
// P = ex2(S); row sums via ones-MMA. 2-stage cp.async.
// ===========================================================================
#define AT_ARR 9216                        // [64][72] fp16 bytes
#define AT_STAGE (2*AT_ARR)                // 18432 (K, V)
#define AT_SMEM (2*AT_STAGE)               // 36864 (also fits Q 256x72 fp16)
#define NT (SLEN/64)                       // 64 k-tiles
#define ONES2 0x3C003C00u                  // fp16x2 {1,1}

__global__ void __launch_bounds__(256, 2) attn_mma(float* __restrict__ out) {
    extern __shared__ char smraw[];
    uint32_t smb = smem_to_u32(smraw);
    int tid = threadIdx.x, lane = tid & 31, warp = tid >> 5;   // warp 0..7
    int q0 = blockIdx.x * 256, h = blockIdx.y, b = blockIdx.z;
    int bh = b * NHEAD + h;

    int l8 = lane & 7, g4 = lane >> 3;
    int offA = (l8 + ((g4 & 1) ? 8 : 0)) * 72 + ((g4 & 2) ? 8 : 0);
    int offB = (l8 + ((g4 & 2) ? 8 : 0)) * 72 + ((g4 & 1) ? 8 : 0);

    // ---- prologue: stage Q (256x72 = 36864B, overlays both stage bufs) ----
    {
        __half* sQ = (__half*)smraw;
        const __half* Q_g = g_Q + ((size_t)bh*SLEN + q0)*HDIM;
#pragma unroll
        for (int i = 0; i < 8; i++) {
            int e = tid + i * 256;          // 0..2047
            int r = e >> 3, cv = (e & 7) * 8;
            *(uint4*)&sQ[r*72 + cv] = *(const uint4*)&Q_g[r*HDIM + cv];
        }
    }
    __syncthreads();
    uint32_t Qf[4][2][4];
#pragma unroll
    for (int kc = 0; kc < 4; kc++)
#pragma unroll
        for (int rg = 0; rg < 2; rg++) {
            uint32_t base = 2u * (uint32_t)((warp*32 + rg*16)*72 + kc*16 + offA);
            ldsm_x4(Qf[kc][rg], smb + base);
        }
    __syncthreads();   // done reading Q buffer before cp.async overwrites

    const __half* K_g = g_K + (size_t)bh*SLEN*HDIM;
    const __half* V_g = g_V + (size_t)bh*SLEN*HDIM;

    int sr = tid >> 3, sc = (tid & 7) * 8;   // sr 0..31; rows sr, sr+32

    auto issue = [&](int kt, int st) {
        size_t gb = (size_t)kt * 64 * HDIM;
        uint32_t sb = smb + st * AT_STAGE;
        const __half* srcs[2] = {K_g + gb, V_g + gb};
#pragma unroll
        for (int a = 0; a < 2; a++)
#pragma unroll
            for (int rr = 0; rr < 2; rr++) {
                int r = sr + rr*32;
                cpasync16(sb + a*AT_ARR + (r*72 + sc)*2,
                          srcs[a] + (size_t)r*HDIM + sc);
            }
        cp_commit();
    };

    float o[2][8][4] = {};
    float rsacc[2][4] = {};

    issue(0, 0);
    issue(1, 1);

    for (int kt = 0; kt < NT; kt++) {
        if (kt + 1 < NT) asm volatile("cp.async.wait_group 1;" ::: "memory");
        else             asm volatile("cp.async.wait_group 0;" ::: "memory");
        __syncthreads();
        uint32_t sb = smb + (kt & 1) * AT_STAGE;
        uint32_t aK = sb, aV = sb + AT_ARR;

        // ---- S = Q K^T (log2 domain): K frags loaded once, both row-groups ----
        float s[2][8][4] = {};
#pragma unroll
        for (int kc = 0; kc < 4; kc++) {
            uint32_t bhf[4][4];
#pragma unroll
            for (int pr = 0; pr < 4; pr++) {
                uint32_t bbase = 2u * (uint32_t)(pr*16*72 + kc*16 + offB);
                ldsm_x4(bhf[pr], aK + bbase);
            }
#pragma unroll
            for (int rg = 0; rg < 2; rg++)
#pragma unroll
                for (int pr = 0; pr < 4; pr++) {
                    mma_f16(s[rg][2*pr],   Qf[kc][rg], bhf[pr][0], bhf[pr][1]);
                    mma_f16(s[rg][2*pr+1], Qf[kc][rg], bhf[pr][2], bhf[pr][3]);
                }
        }

        // ---- P = ex2(S) : single MUFU per element ----
#pragma unroll
        for (int rg = 0; rg < 2; rg++)
#pragma unroll
            for (int j = 0; j < 8; j++) {
                s[rg][j][0] = ex2(s[rg][j][0]);
                s[rg][j][1] = ex2(s[rg][j][1]);
                s[rg][j][2] = ex2(s[rg][j][2]);
                s[rg][j][3] = ex2(s[rg][j][3]);
            }

        // ---- O += P V ; row sums via ones-MMA ----
#pragma unroll
        for (int kc2 = 0; kc2 < 4; kc2++) {
            uint32_t ah[2][4];
#pragma unroll
            for (int rg = 0; rg < 2; rg++) {
                ah[rg][0] = pack2h(s[rg][2*kc2][0],   s[rg][2*kc2][1]);
                ah[rg][1] = pack2h(s[rg][2*kc2][2],   s[rg][2*kc2][3]);
                ah[rg][2] = pack2h(s[rg][2*kc2+1][0], s[rg][2*kc2+1][1]);
                ah[rg][3] = pack2h(s[rg][2*kc2+1][2], s[rg][2*kc2+1][3]);
            }
            uint32_t vhf[4][4];
#pragma unroll
            for (int pr = 0; pr < 4; pr++) {
                uint32_t vb = 2u * (uint32_t)(kc2*16*72 + pr*16 + offA);
                ldsm_x4_t(vhf[pr], aV + vb);
            }
#pragma unroll
            for (int rg = 0; rg < 2; rg++)
#pragma unroll
                for (int pr = 0; pr < 4; pr++) {
                    mma_f16(o[rg][2*pr],   ah[rg], vhf[pr][0], vhf[pr][1]);
                    mma_f16(o[rg][2*pr+1], ah[rg], vhf[pr][2], vhf[pr][3]);
                }
#pragma unroll
            for (int rg = 0; rg < 2; rg++)
                mma_f16(rsacc[rg], ah[rg], ONES2, ONES2);
        }
        __syncthreads();
        if (kt + 2 < NT) issue(kt + 2, kt & 1);
    }

    // ---- epilogue (row sums already reduced by the ones-MMA) ----
    int g = lane >> 2, t = lane & 3;
#pragma unroll
    for (int rg = 0; rg < 2; rg++) {
        float i0 = 1.f / rsacc[rg][0];
        float i1 = 1.f / rsacc[rg][2];
        int row = q0 + warp*32 + rg*16 + g;
        float* d0 = out + (size_t)(b*SLEN + row)*EDIM + h*HDIM;
        float* d1 = d0 + 8*EDIM;
#pragma unroll
        for (int j = 0; j < 8; j++) {
            int cidx = j*8 + 2*t;
            *(float2*)&d0[cidx] = make_float2(o[rg][j][0]*i0, o[rg][j][1]*i0);
            *(float2*)&d1[cidx] = make_float2(o[rg][j][2]*i1, o[rg][j][3]*i1);
        }
    }
}

// ===========================================================================
extern "C" void kernel_launch(void* const* d_in, const int* in_sizes, int n_in,
                              void* d_out, int out_size) {
    const float* rot = (const float*)d_in[0];
    const float* ent = (const float*)d_in[1];
    const float* x   = (const float*)d_in[2];
    const float* wq  = (const float*)d_in[3];
    const float* wk  = (const float*)d_in[4];
    const float* wv  = (const float*)d_in[5];
    float* out = (float*)d_out;

    cudaFuncSetAttribute(proj_mma, cudaFuncAttributeMaxDynamicSharedMemorySize, PJ_SMEM);
    cudaFuncSetAttribute(attn_mma, cudaFuncAttributeMaxDynamicSharedMemorySize, AT_SMEM);

    __half *xh, *xl, *bv;
    cudaGetSymbolAddress((void**)&xh, g_xh);
    cudaGetSymbolAddress((void**)&xl, g_xl);
    cudaGetSymbolAddress((void**)&bv, g_BtV);

    split_f16<<<(NROWS*EDIM/4 + 255)/256, 256>>>(x, xh, xl, NROWS*EDIM/4);
    conv_f16<<<(EDIM*EDIM/4 + 255)/256, 256>>>(wv, bv, EDIM*EDIM/4);
    fuse_weights2<<<dim3(8, 8, 2), 256>>>(wq, wk, rot, ent);
    proj_mma<<<dim3(NROWS/128, EDIM/128, 3), 256, PJ_SMEM>>>();
    attn_mma<<<dim3(SLEN/256, NHEAD, BATCH), 256, AT_SMEM>>>(out);
}

// round 16
// speedup vs baseline: 1.1922x; 1.1922x over previous
#include <cuda_runtime.h>
#include <cuda_fp16.h>
#include <cstdint>

#define EDIM 512
#define SLEN 4096
#define BATCH 2
#define NHEAD 8
#define HDIM 64
#define NROWS (BATCH*SLEN)   // 8192
#define QSCALE 0.1803368801111904f   // log2(e)/8, folded into BtQ

// ===========================================================================
// Device scratch (allocation-free rule). Everything single fp16.
// ===========================================================================
__device__ __half g_x16[NROWS*EDIM];
__device__ __half g_BtQ[EDIM*EDIM], g_BtK[EDIM*EDIM], g_BtV[EDIM*EDIM];
__device__ __half g_Q[NROWS*EDIM], g_K[NROWS*EDIM], g_V[NROWS*EDIM];

// ===========================================================================
// helpers
// ===========================================================================
__device__ __forceinline__ uint32_t smem_to_u32(const void* p) {
    uint32_t a;
    asm("{ .reg .u64 t; cvta.to.shared.u64 t, %1; cvt.u32.u64 %0, t; }"
        : "=r"(a) : "l"(p));
    return a;
}
__device__ __forceinline__ uint32_t pack2h(float a, float b) {
    __half2 t = __floats2half2_rn(a, b);
    return *reinterpret_cast<uint32_t*>(&t);
}
__device__ __forceinline__ float ex2(float x) {
    float y;
    asm("ex2.approx.f32 %0, %1;" : "=f"(y) : "f"(x));
    return y;
}
__device__ __forceinline__ void mma_f16(float* c, const uint32_t* a,
                                        uint32_t b0, uint32_t b1) {
    asm volatile(
        "mma.sync.aligned.m16n8k16.row.col.f32.f16.f16.f32 "
        "{%0,%1,%2,%3}, {%4,%5,%6,%7}, {%8,%9}, {%0,%1,%2,%3};"
        : "+f"(c[0]), "+f"(c[1]), "+f"(c[2]), "+f"(c[3])
        : "r"(a[0]), "r"(a[1]), "r"(a[2]), "r"(a[3]), "r"(b0), "r"(b1));
}
__device__ __forceinline__ void ldsm_x4(uint32_t* r, uint32_t addr) {
    asm volatile("ldmatrix.sync.aligned.m8n8.x4.shared.b16 {%0,%1,%2,%3}, [%4];"
        : "=r"(r[0]), "=r"(r[1]), "=r"(r[2]), "=r"(r[3]) : "r"(addr));
}
__device__ __forceinline__ void ldsm_x4_t(uint32_t* r, uint32_t addr) {
    asm volatile("ldmatrix.sync.aligned.m8n8.x4.trans.shared.b16 {%0,%1,%2,%3}, [%4];"
        : "=r"(r[0]), "=r"(r[1]), "=r"(r[2]), "=r"(r[3]) : "r"(addr));
}
__device__ __forceinline__ void cpasync16(uint32_t dst, const void* src) {
    asm volatile("cp.async.cg.shared.global [%0], [%1], 16;"
                 :: "r"(dst), "l"(src) : "memory");
}
__device__ __forceinline__ void cp_commit() {
    asm volatile("cp.async.commit_group;" ::: "memory");
}

// ===========================================================================
// prep: fp32 -> fp16
// ===========================================================================
__global__ void conv_f16(const float* __restrict__ src,
                         __half* __restrict__ dst, int n4) {
    int i = blockIdx.x * blockDim.x + threadIdx.x;
    if (i >= n4) return;
    float4 v = reinterpret_cast<const float4*>(src)[i];
    reinterpret_cast<uint2*>(dst)[i] =
        make_uint2(pack2h(v.x, v.y), pack2h(v.z, v.w));
}

// ===========================================================================
// fuse: Bt[j][i] = sum_e W[e][i] * R[e][j]  (fp32 compute, fp16 out)
// z=0 output is pre-scaled by QSCALE = log2(e)/8 (softmax fold).
// ===========================================================================
__global__ void fuse_weights2(const float* __restrict__ wq,
                              const float* __restrict__ wk,
                              const float* __restrict__ rot,
                              const float* __restrict__ ent) {
    int z = blockIdx.z;
    const float* W = z ? wk : wq;
    const float* R = z ? ent : rot;
    __half* B = z ? g_BtK : g_BtQ;
    float oscale = z ? 1.0f : QSCALE;
    int i0 = blockIdx.y * 64, j0 = blockIdx.x * 64;
    int tid = threadIdx.x;

    __shared__ float As[16*68], Bs[16*68], T[64*65];
    int tm = (tid >> 4) << 2, tn = (tid & 15) << 2;
    int lr = tid >> 4, lc = (tid & 15) << 2;
    float acc[4][4] = {};

    for (int k0 = 0; k0 < EDIM; k0 += 16) {
        *(float4*)&As[lr*68 + lc] = *(const float4*)&W[(k0+lr)*EDIM + i0 + lc];
        *(float4*)&Bs[lr*68 + lc] = *(const float4*)&R[(k0+lr)*EDIM + j0 + lc];
        __syncthreads();
#pragma unroll
        for (int k = 0; k < 16; k++) {
            float4 a = *(const float4*)&As[k*68 + tm];
            float4 b = *(const float4*)&Bs[k*68 + tn];
            float av[4] = {a.x,a.y,a.z,a.w};
            float bv[4] = {b.x,b.y,b.z,b.w};
#pragma unroll
            for (int i = 0; i < 4; i++)
#pragma unroll
                for (int j = 0; j < 4; j++)
                    acc[i][j] = fmaf(av[i], bv[j], acc[i][j]);
        }
        __syncthreads();
    }
#pragma unroll
    for (int i = 0; i < 4; i++)
#pragma unroll
        for (int j = 0; j < 4; j++)
            T[(tm+i)*65 + tn+j] = acc[i][j];
    __syncthreads();
#pragma unroll
    for (int r = 0; r < 4; r++) {
        int jrow = j0 + tm + r;
#pragma unroll
        for (int c = 0; c < 4; c += 2) {
            float v0 = T[(tn+c)*65 + (tm+r)] * oscale;
            float v1 = T[(tn+c+1)*65 + (tm+r)] * oscale;
            *reinterpret_cast<uint32_t*>(&B[jrow*EDIM + i0 + tn + c]) =
                pack2h(v0, v1);
        }
    }
}

// ===========================================================================
// proj: D = x @ M, 128x128 tile/CTA, 256 threads / 8 warps (R7 layout),
// fp16 1-pass (A = x fp16, B = Bt fp16). 2-stage cp.async.
// ===========================================================================
#define PJ_ARR 10240                       // bytes per array [128][40] fp16
#define PJ_STAGE (2*PJ_ARR)                // 20480 (A, B)
#define PJ_SMEM (2*PJ_STAGE)               // 40960

__global__ void __launch_bounds__(256, 2) proj_mma() {
    extern __shared__ char smraw[];
    uint32_t smb = smem_to_u32(smraw);
    int tid = threadIdx.x, lane = tid & 31, warp = tid >> 5;
    int rw = warp & 3, ch = warp >> 2;
    int m0 = blockIdx.x * 128, n0 = blockIdx.y * 128, z = blockIdx.z;

    const __half* B_g = (z==0) ? g_BtQ : (z==1) ? g_BtK : g_BtV;
    __half* D_g = (z==0) ? g_Q : (z==1) ? g_K : g_V;

    int l8 = lane & 7, g4 = lane >> 3;
    int offA = (l8 + ((g4 & 1) ? 8 : 0)) * 40 + ((g4 & 2) ? 8 : 0);
    int offB = (l8 + ((g4 & 2) ? 8 : 0)) * 40 + ((g4 & 1) ? 8 : 0);

    int sr = tid >> 2, sc = (tid & 3) * 8;   // rows sr, sr+64

    auto issue = [&](int it, int st) {
        int k0 = it * 32;
        uint32_t sb = smb + st * PJ_STAGE;
        const __half* srcs[2] = {
            g_x16 + (size_t)(m0)*EDIM + k0,
            B_g + (size_t)(n0)*EDIM + k0 };
#pragma unroll
        for (int a = 0; a < 2; a++) {
            cpasync16(sb + a*PJ_ARR + (sr*40 + sc)*2, srcs[a] + (size_t)sr*EDIM + sc);
            cpasync16(sb + a*PJ_ARR + ((sr+64)*40 + sc)*2, srcs[a] + (size_t)(sr+64)*EDIM + sc);
        }
        cp_commit();
    };

    float c[2][8][4] = {};
    issue(0, 0);
    issue(1, 1);

    for (int it = 0; it < 16; it++) {
        if (it + 1 < 16) asm volatile("cp.async.wait_group 1;" ::: "memory");
        else             asm volatile("cp.async.wait_group 0;" ::: "memory");
        __syncthreads();
        uint32_t sb = smb + (it & 1) * PJ_STAGE;
        uint32_t aA = sb, aB = sb + PJ_ARR;

#pragma unroll
        for (int kc = 0; kc < 2; kc++) {
            uint32_t ahf[2][4];
#pragma unroll
            for (int rg = 0; rg < 2; rg++) {
                uint32_t abase = 2u * (uint32_t)((rw*32 + rg*16)*40 + kc*16 + offA);
                ldsm_x4(ahf[rg], aA + abase);
            }
#pragma unroll
            for (int pp = 0; pp < 2; pp++) {
                uint32_t bhf[2][4];
#pragma unroll
                for (int q = 0; q < 2; q++) {
                    int pr = pp*2 + q;
                    uint32_t bbase = 2u * (uint32_t)((ch*64 + pr*16)*40 + kc*16 + offB);
                    ldsm_x4(bhf[q], aB + bbase);
                }
#pragma unroll
                for (int rg = 0; rg < 2; rg++)
#pragma unroll
                    for (int q = 0; q < 2; q++) {
                        int j = (pp*2 + q)*2;
                        mma_f16(c[rg][j],   ahf[rg], bhf[q][0], bhf[q][1]);
                        mma_f16(c[rg][j+1], ahf[rg], bhf[q][2], bhf[q][3]);
                    }
            }
        }
        __syncthreads();
        if (it + 2 < 16) issue(it + 2, it & 1);
    }

    int g = lane >> 2, t = lane & 3;
#pragma unroll
    for (int rg = 0; rg < 2; rg++) {
        int mr = m0 + rw*32 + rg*16 + g;
        int b = mr >> 12, s = mr & (SLEN - 1);
#pragma unroll
        for (int j = 0; j < 8; j++) {
            int n = n0 + ch*64 + j*8 + 2*t;
            int hh = n >> 6, d = n & 63;
            size_t i0 = ((size_t)(b*NHEAD + hh)*SLEN + s)*HDIM + d;
            size_t i1 = i0 + 8*HDIM;
            *reinterpret_cast<uint32_t*>(&D_g[i0]) = pack2h(c[rg][j][0], c[rg][j][1]);
            *reinterpret_cast<uint32_t*>(&D_g[i1]) = pack2h(c[rg][j][2], c[rg][j][3]);
        }
    }
}

// ===========================================================================
// attention (R14 exact): CTA = 128 q-rows, 128 threads / 4 warps, 2 CTAs/SM.
// warp = 32 q-rows (2 x m16 row-groups) x full 64 S-cols.
// Q pre-scaled by log2(e)/8 => P = ex2(S). Row sums via ones-MMA.
// ===========================================================================
#define AT_ARR 9216                        // [64][72] fp16 bytes
#define AT_STAGE (2*AT_ARR)                // 18432 (K, V)
#define AT_SMEM (2*AT_STAGE)               // 36864
#define NT (SLEN/64)                       // 64 k-tiles
#define ONES2 0x3C003C00u                  // fp16x2 {1,1}

__global__ void __launch_bounds__(128, 2) attn_mma(float* __restrict__ out) {
    extern __shared__ char smraw[];
    uint32_t smb = smem_to_u32(smraw);
    int tid = threadIdx.x, lane = tid & 31, warp = tid >> 5;   // warp 0..3
    int q0 = blockIdx.x * 128, h = blockIdx.y, b = blockIdx.z;
    int bh = b * NHEAD + h;

    int l8 = lane & 7, g4 = lane >> 3;
    int offA = (l8 + ((g4 & 1) ? 8 : 0)) * 72 + ((g4 & 2) ? 8 : 0);
    int offB = (l8 + ((g4 & 2) ? 8 : 0)) * 72 + ((g4 & 1) ? 8 : 0);

    // ---- prologue: stage Q (128x64) into smem (overlaps stage bufs), frags ----
    {
        __half* sQ = (__half*)smraw;
        const __half* Q_g = g_Q + ((size_t)bh*SLEN + q0)*HDIM;
#pragma unroll
        for (int i = 0; i < 8; i++) {
            int e = tid + i * 128;          // 0..1023
            int r = e >> 3, cv = (e & 7) * 8;
            *(uint4*)&sQ[r*72 + cv] = *(const uint4*)&Q_g[r*HDIM + cv];
        }
    }
    __syncthreads();
    uint32_t Qf[4][2][4];
#pragma unroll
    for (int kc = 0; kc < 4; kc++)
#pragma unroll
        for (int rg = 0; rg < 2; rg++) {
            uint32_t base = 2u * (uint32_t)((warp*32 + rg*16)*72 + kc*16 + offA);
            ldsm_x4(Qf[kc][rg], smb + base);
        }
    __syncthreads();   // done reading Q buffer before cp.async overwrites

    const __half* K_g = g_K + (size_t)bh*SLEN*HDIM;
    const __half* V_g = g_V + (size_t)bh*SLEN*HDIM;

    int sr = tid >> 3, sc = (tid & 7) * 8;   // sr 0..15; rows sr+{0,16,32,48}

    auto issue = [&](int kt, int st) {
        size_t gb = (size_t)kt * 64 * HDIM;
        uint32_t sb = smb + st * AT_STAGE;
        const __half* srcs[2] = {K_g + gb, V_g + gb};
#pragma unroll
        for (int a = 0; a < 2; a++)
#pragma unroll
            for (int rr = 0; rr < 4; rr++) {
                int r = sr + rr*16;
                cpasync16(sb + a*AT_ARR + (r*72 + sc)*2,
                          srcs[a] + (size_t)r*HDIM + sc);
            }
        cp_commit();
    };

    float o[2][8][4] = {};
    float rsacc[2][4] = {};

    issue(0, 0);
    issue(1, 1);

    for (int kt = 0; kt < NT; kt++) {
        if (kt + 1 < NT) asm volatile("cp.async.wait_group 1;" ::: "memory");
        else             asm volatile("cp.async.wait_group 0;" ::: "memory");
        __syncthreads();
        uint32_t sb = smb + (kt & 1) * AT_STAGE;
        uint32_t aK = sb, aV = sb + AT_ARR;

        // ---- S = Q K^T (log2 domain): K frags loaded once, both row-groups ----
        float s[2][8][4] = {};
#pragma unroll
        for (int kc = 0; kc < 4; kc++) {
            uint32_t bhf[4][4];
#pragma unroll
            for (int pr = 0; pr < 4; pr++) {
                uint32_t bbase = 2u * (uint32_t)(pr*16*72 + kc*16 + offB);
                ldsm_x4(bhf[pr], aK + bbase);
            }
#pragma unroll
            for (int rg = 0; rg < 2; rg++)
#pragma unroll
                for (int pr = 0; pr < 4; pr++) {
                    mma_f16(s[rg][2*pr],   Qf[kc][rg], bhf[pr][0], bhf[pr][1]);
                    mma_f16(s[rg][2*pr+1], Qf[kc][rg], bhf[pr][2], bhf[pr][3]);
                }
        }

        // ---- P = ex2(S) : single MUFU per element ----
#pragma unroll
        for (int rg = 0; rg < 2; rg++)
#pragma unroll
            for (int j = 0; j < 8; j++) {
                s[rg][j][0] = ex2(s[rg][j][0]);
                s[rg][j][1] = ex2(s[rg][j][1]);
                s[rg][j][2] = ex2(s[rg][j][2]);
                s[rg][j][3] = ex2(s[rg][j][3]);
            }

        // ---- O += P V ; row sums via ones-MMA ----
#pragma unroll
        for (int kc2 = 0; kc2 < 4; kc2++) {
            uint32_t ah[2][4];
#pragma unroll
            for (int rg = 0; rg < 2; rg++) {
                ah[rg][0] = pack2h(s[rg][2*kc2][0],   s[rg][2*kc2][1]);
                ah[rg][1] = pack2h(s[rg][2*kc2][2],   s[rg][2*kc2][3]);
                ah[rg][2] = pack2h(s[rg][2*kc2+1][0], s[rg][2*kc2+1][1]);
                ah[rg][3] = pack2h(s[rg][2*kc2+1][2], s[rg][2*kc2+1][3]);
            }
            uint32_t vhf[4][4];
#pragma unroll
            for (int pr = 0; pr < 4; pr++) {
                uint32_t vb = 2u * (uint32_t)(kc2*16*72 + pr*16 + offA);
                ldsm_x4_t(vhf[pr], aV + vb);
            }
#pragma unroll
            for (int rg = 0; rg < 2; rg++)
#pragma unroll
                for (int pr = 0; pr < 4; pr++) {
                    mma_f16(o[rg][2*pr],   ah[rg], vhf[pr][0], vhf[pr][1]);
                    mma_f16(o[rg][2*pr+1], ah[rg], vhf[pr][2], vhf[pr][3]);
                }
#pragma unroll
            for (int rg = 0; rg < 2; rg++)
                mma_f16(rsacc[rg], ah[rg], ONES2, ONES2);
        }
        __syncthreads();
        if (kt + 2 < NT) issue(kt + 2, kt & 1);
    }

    // ---- epilogue (row sums already reduced by the ones-MMA) ----
    int g = lane >> 2, t = lane & 3;
#pragma unroll
    for (int rg = 0; rg < 2; rg++) {
        float i0 = 1.f / rsacc[rg][0];
        float i1 = 1.f / rsacc[rg][2];
        int row = q0 + warp*32 + rg*16 + g;
        float* d0 = out + (size_t)(b*SLEN + row)*EDIM + h*HDIM;
        float* d1 = d0 + 8*EDIM;
#pragma unroll
        for (int j = 0; j < 8; j++) {
            int cidx = j*8 + 2*t;
            *(float2*)&d0[cidx] = make_float2(o[rg][j][0]*i0, o[rg][j][1]*i0);
            *(float2*)&d1[cidx] = make_float2(o[rg][j][2]*i1, o[rg][j][3]*i1);
        }
    }
}

// ===========================================================================
extern "C" void kernel_launch(void* const* d_in, const int* in_sizes, int n_in,
                              void* d_out, int out_size) {
    const float* rot = (const float*)d_in[0];
    const float* ent = (const float*)d_in[1];
    const float* x   = (const float*)d_in[2];
    const float* wq  = (const float*)d_in[3];
    const float* wk  = (const float*)d_in[4];
    const float* wv  = (const float*)d_in[5];
    float* out = (float*)d_out;

    cudaFuncSetAttribute(proj_mma, cudaFuncAttributeMaxDynamicSharedMemorySize, PJ_SMEM);
    cudaFuncSetAttribute(attn_mma, cudaFuncAttributeMaxDynamicSharedMemorySize, AT_SMEM);

    __half *x16, *bv;
    cudaGetSymbolAddress((void**)&x16, g_x16);
    cudaGetSymbolAddress((void**)&bv, g_BtV);

    conv_f16<<<(NROWS*EDIM/4 + 255)/256, 256>>>(x, x16, NROWS*EDIM/4);
    conv_f16<<<(EDIM*EDIM/4 + 255)/256, 256>>>(wv, bv, EDIM*EDIM/4);
    fuse_weights2<<<dim3(8, 8, 2), 256>>>(wq, wk, rot, ent);
    proj_mma<<<dim3(NROWS/128, EDIM/128, 3), 256, PJ_SMEM>>>();
    attn_mma<<<dim3(SLEN/128, NHEAD, BATCH), 128, AT_SMEM>>>(out);
}